// round 3
// baseline (speedup 1.0000x reference)
#include <cuda_runtime.h>
#include <math.h>

#define BATCH 8
#define CHAN  128
#define HDIM  64
#define WDIM  64
#define LLEN  4096
#define NHEAD 8
#define NPTS  8
#define DHEAD 16

typedef unsigned long long u64;

__device__ float g_value[BATCH * LLEN * CHAN];
__device__ float g_off  [BATCH * LLEN * NHEAD * NPTS * 2];
__device__ float g_attn [BATCH * LLEN * NHEAD * NPTS];
__device__ float g_mid  [BATCH * LLEN * CHAN];

__device__ __forceinline__ void fma2(u64& d, u64 a, u64 b) {
    asm("fma.rn.f32x2 %0, %1, %2, %0;" : "+l"(d) : "l"(a), "l"(b));
}
__device__ __forceinline__ u64 dup2(float x) {
    u64 r; asm("mov.b64 %0, {%1, %1};" : "=l"(r) : "f"(x)); return r;
}
__device__ __forceinline__ void unpack2(u64 v, float& lo, float& hi) {
    asm("mov.b64 {%0, %1}, %2;" : "=f"(lo), "=f"(hi) : "l"(v));
}

// ---------------------------------------------------------------------------
// Kernel 1: fused projections, 128l x 64n tile, 256 thr, FFMA2 mainloop.
// blockIdx.y = n-tile (0,1: W_val/nbr; 2,3: W_off/ext; 4: W_attn/ext)
// ---------------------------------------------------------------------------
__global__ __launch_bounds__(256)
void proj_kernel(const float* __restrict__ nbr, const float* __restrict__ ext,
                 const float* __restrict__ Wv, const float* __restrict__ bv,
                 const float* __restrict__ Wo, const float* __restrict__ bo,
                 const float* __restrict__ Wa, const float* __restrict__ ba)
{
    __shared__ float As[16][128];
    __shared__ u64   Bs2[16][64];     // weights, each value duplicated into a f32x2

    const int nt  = blockIdx.y;
    const int b   = blockIdx.x >> 5;
    const int l0  = (blockIdx.x & 31) << 7;
    const int tid = threadIdx.x;
    const int tx  = tid & 15;
    const int ty  = tid >> 4;

    const float* Asrc = (nt < 2) ? nbr : ext;
    const float* Bsrc;
    int bstride, bcol;
    if (nt == 0)      { Bsrc = Wv; bstride = 128; bcol = 0;  }
    else if (nt == 1) { Bsrc = Wv; bstride = 128; bcol = 64; }
    else if (nt == 2) { Bsrc = Wo; bstride = 128; bcol = 0;  }
    else if (nt == 3) { Bsrc = Wo; bstride = 128; bcol = 64; }
    else              { Bsrc = Wa; bstride = 64;  bcol = 0;  }

    u64 acc2[4][4];
    #pragma unroll
    for (int i = 0; i < 4; i++)
        #pragma unroll
        for (int j = 0; j < 4; j++) acc2[i][j] = 0ull;

    for (int k0 = 0; k0 < CHAN; k0 += 16) {
        #pragma unroll
        for (int i = 0; i < 2; i++) {
            int fid = tid + i * 256;
            int row = fid >> 5, c4 = (fid & 31) << 2;
            *(float4*)&As[row][c4] =
                *(const float4*)&Asrc[(size_t)(b * CHAN + k0 + row) * LLEN + l0 + c4];
        }
        {
            int row = tid >> 4, c4 = (tid & 15) << 2;
            float4 v = *(const float4*)&Bsrc[(k0 + row) * bstride + bcol + c4];
            Bs2[row][c4]     = dup2(v.x);
            Bs2[row][c4 + 1] = dup2(v.y);
            Bs2[row][c4 + 2] = dup2(v.z);
            Bs2[row][c4 + 3] = dup2(v.w);
        }
        __syncthreads();

        #pragma unroll
        for (int kk = 0; kk < 16; kk++) {
            const u64* arow = (const u64*)&As[kk][ty * 8];   // 4 packed l-pairs
            u64 a2[4], b2[4];
            #pragma unroll
            for (int i = 0; i < 4; i++) a2[i] = arow[i];
            #pragma unroll
            for (int j = 0; j < 4; j++) b2[j] = Bs2[kk][tx * 4 + j];
            #pragma unroll
            for (int i = 0; i < 4; i++)
                #pragma unroll
                for (int j = 0; j < 4; j++)
                    fma2(acc2[i][j], a2[i], b2[j]);
        }
        __syncthreads();
    }

    float acc[8][4];
    #pragma unroll
    for (int i = 0; i < 4; i++)
        #pragma unroll
        for (int j = 0; j < 4; j++)
            unpack2(acc2[i][j], acc[2 * i][j], acc[2 * i + 1][j]);

    if (nt < 2) {
        int n = nt * 64 + tx * 4;
        float4 bia = *(const float4*)&bv[n];
        #pragma unroll
        for (int i = 0; i < 8; i++) {
            int l = l0 + ty * 8 + i;
            float4 v = {acc[i][0] + bia.x, acc[i][1] + bia.y,
                        acc[i][2] + bia.z, acc[i][3] + bia.w};
            *(float4*)&g_value[(size_t)(b * LLEN + l) * 128 + n] = v;
        }
    } else if (nt < 4) {
        int m = (nt - 2) * 64 + tx * 4;
        float4 bia = *(const float4*)&bo[m];
        #pragma unroll
        for (int i = 0; i < 8; i++) {
            int l = l0 + ty * 8 + i;
            float4 v = {10.0f * tanhf(acc[i][0] + bia.x), 10.0f * tanhf(acc[i][1] + bia.y),
                        10.0f * tanhf(acc[i][2] + bia.z), 10.0f * tanhf(acc[i][3] + bia.w)};
            *(float4*)&g_off[(size_t)(b * LLEN + l) * 128 + m] = v;
        }
    } else {
        int m = tx * 4;
        float4 bia = *(const float4*)&ba[m];
        #pragma unroll
        for (int i = 0; i < 8; i++) {
            int l = l0 + ty * 8 + i;
            float4 v = {acc[i][0] + bia.x, acc[i][1] + bia.y,
                        acc[i][2] + bia.z, acc[i][3] + bia.w};
            *(float4*)&g_attn[(size_t)(b * LLEN + l) * 64 + m] = v;
        }
    }
}

// ---------------------------------------------------------------------------
// Kernel 2: softmax + bilinear sampling. One block per (b, 8x8 tile).
// Phase 2: one warp per l (32 lanes x float4 = 128 ch), branchless corners.
// ---------------------------------------------------------------------------
__global__ __launch_bounds__(256)
void sample_kernel()
{
    __shared__ float sw [64 * 64];
    __shared__ float spx[64 * 64];
    __shared__ float spy[64 * 64];

    const int b    = blockIdx.y;
    const int tile = blockIdx.x;
    const int x0t  = (tile & 7) * 8;
    const int y0t  = (tile >> 3) * 8;
    const int tid  = threadIdx.x;

    // ---- Phase 1: softmax + absolute coords ----
    #pragma unroll
    for (int i = 0; i < 2; i++) {
        int task  = tid + i * 256;
        int l_loc = task >> 3;
        int h     = task & 7;
        int lx = x0t + (l_loc & 7);
        int ly = y0t + (l_loc >> 3);
        size_t bl = (size_t)b * LLEN + ly * WDIM + lx;

        const float* op = g_off + bl * 128 + h * 16;
        float4 o0 = *(const float4*)(op);
        float4 o1 = *(const float4*)(op + 4);
        float4 o2 = *(const float4*)(op + 8);
        float4 o3 = *(const float4*)(op + 12);
        float ox[8] = {o0.x, o0.z, o1.x, o1.z, o2.x, o2.z, o3.x, o3.z};
        float oy[8] = {o0.y, o0.w, o1.y, o1.w, o2.y, o2.w, o3.y, o3.w};

        const float* ap = g_attn + bl * 64 + h * 8;
        float4 g0 = *(const float4*)(ap);
        float4 g1 = *(const float4*)(ap + 4);
        float lg[8] = {g0.x, g0.y, g0.z, g0.w, g1.x, g1.y, g1.z, g1.w};

        float m = -1e30f;
        #pragma unroll
        for (int p = 0; p < 8; p++) m = fmaxf(m, lg[p]);
        float e[8], s = 0.f;
        #pragma unroll
        for (int p = 0; p < 8; p++) { e[p] = __expf(lg[p] - m); s += e[p]; }
        float inv = 1.0f / s;

        int base = l_loc * 64 + h * 8;
        #pragma unroll
        for (int p = 0; p < 8; p++) {
            sw [base + p] = e[p] * inv;
            spx[base + p] = (float)lx + ox[p];
            spy[base + p] = (float)ly + oy[p];
        }
    }
    __syncthreads();

    // ---- Phase 2 ----
    const int warp = tid >> 5;
    const int lane = tid & 31;
    const int h    = lane >> 2;
    const int ch   = h * 16 + (lane & 3) * 4;
    const float* vbase = g_value + (size_t)b * LLEN * CHAN + ch;

    #pragma unroll 1
    for (int it = 0; it < 8; it++) {
        int l_loc = it * 8 + warp;     // 8 warps cover one tile row concurrently
        int lx = x0t + (l_loc & 7);
        int ly = y0t + (l_loc >> 3);

        float4 acc = {0.f, 0.f, 0.f, 0.f};
        int sbase = l_loc * 64 + h * 8;
        #pragma unroll
        for (int p = 0; p < 8; p++) {
            float wt = sw [sbase + p];
            float px = spx[sbase + p];
            float py = spy[sbase + p];
            float x0f = floorf(px), y0f = floorf(py);
            float fx = px - x0f, fy = py - y0f;
            int x0 = (int)x0f, y0 = (int)y0f;

            int xc0 = min(max(x0, 0), WDIM - 1);
            int xc1 = min(max(x0 + 1, 0), WDIM - 1);
            int yc0 = min(max(y0, 0), HDIM - 1);
            int yc1 = min(max(y0 + 1, 0), HDIM - 1);
            float mx0 = (x0 >= 0  && x0 < WDIM)      ? 1.f : 0.f;
            float mx1 = (x0 >= -1 && x0 < WDIM - 1)  ? 1.f : 0.f;
            float my0 = (y0 >= 0  && y0 < HDIM)      ? 1.f : 0.f;
            float my1 = (y0 >= -1 && y0 < HDIM - 1)  ? 1.f : 0.f;

            float gx0 = 1.f - fx, gy0 = 1.f - fy;
            float w00 = wt * gx0 * gy0 * mx0 * my0;
            float w10 = wt * fx  * gy0 * mx1 * my0;
            float w01 = wt * gx0 * fy  * mx0 * my1;
            float w11 = wt * fx  * fy  * mx1 * my1;

            int r0 = yc0 * WDIM, r1 = yc1 * WDIM;
            float4 v00 = *(const float4*)(vbase + (size_t)(r0 + xc0) * CHAN);
            float4 v10 = *(const float4*)(vbase + (size_t)(r0 + xc1) * CHAN);
            float4 v01 = *(const float4*)(vbase + (size_t)(r1 + xc0) * CHAN);
            float4 v11 = *(const float4*)(vbase + (size_t)(r1 + xc1) * CHAN);

            acc.x = fmaf(w00, v00.x, fmaf(w10, v10.x, fmaf(w01, v01.x, fmaf(w11, v11.x, acc.x))));
            acc.y = fmaf(w00, v00.y, fmaf(w10, v10.y, fmaf(w01, v01.y, fmaf(w11, v11.y, acc.y))));
            acc.z = fmaf(w00, v00.z, fmaf(w10, v10.z, fmaf(w01, v01.z, fmaf(w11, v11.z, acc.z))));
            acc.w = fmaf(w00, v00.w, fmaf(w10, v10.w, fmaf(w01, v01.w, fmaf(w11, v11.w, acc.w))));
        }
        *(float4*)&g_mid[((size_t)b * LLEN + ly * WDIM + lx) * 128 + ch] = acc;
    }
}

// ---------------------------------------------------------------------------
// Kernel 3: output projection, 64l x 128n tile, FFMA2 (packed along n).
// ---------------------------------------------------------------------------
__global__ __launch_bounds__(256)
void out_kernel(const float* __restrict__ Wout, const float* __restrict__ bout,
                float* __restrict__ out)
{
    __shared__ float As[64][17];
    __shared__ float Bs[16][128];

    const int b   = blockIdx.x >> 6;
    const int l0  = (blockIdx.x & 63) << 6;
    const int tid = threadIdx.x;
    const int tx  = tid & 15;
    const int ty  = tid >> 4;

    u64 acc2[4][4];
    #pragma unroll
    for (int i = 0; i < 4; i++)
        #pragma unroll
        for (int j = 0; j < 4; j++) acc2[i][j] = 0ull;

    for (int k0 = 0; k0 < CHAN; k0 += 16) {
        {
            int row = tid >> 2, cg = (tid & 3) << 2;
            float4 v = *(const float4*)&g_mid[(size_t)(b * LLEN + l0 + row) * 128 + k0 + cg];
            As[row][cg] = v.x; As[row][cg + 1] = v.y;
            As[row][cg + 2] = v.z; As[row][cg + 3] = v.w;
        }
        #pragma unroll
        for (int i = 0; i < 2; i++) {
            int fid = tid + i * 256;
            int row = fid >> 5, c4 = (fid & 31) << 2;
            *(float4*)&Bs[row][c4] = *(const float4*)&Wout[(k0 + row) * 128 + c4];
        }
        __syncthreads();

        #pragma unroll
        for (int kk = 0; kk < 16; kk++) {
            u64 a2[4], w2[4];
            #pragma unroll
            for (int j = 0; j < 4; j++) a2[j] = dup2(As[tx + 16 * j][kk]);
            const u64* wrow = (const u64*)&Bs[kk][ty * 8];   // 4 packed n-pairs
            #pragma unroll
            for (int i = 0; i < 4; i++) w2[i] = wrow[i];
            #pragma unroll
            for (int i = 0; i < 4; i++)
                #pragma unroll
                for (int j = 0; j < 4; j++)
                    fma2(acc2[i][j], w2[i], a2[j]);
        }
        __syncthreads();
    }

    #pragma unroll
    for (int i = 0; i < 4; i++) {
        float blo = bout[ty * 8 + 2 * i];
        float bhi = bout[ty * 8 + 2 * i + 1];
        #pragma unroll
        for (int j = 0; j < 4; j++) {
            float lo, hi;
            unpack2(acc2[i][j], lo, hi);
            size_t col = l0 + tx + 16 * j;
            out[((size_t)(b * CHAN + ty * 8 + 2 * i))     * LLEN + col] = lo + blo;
            out[((size_t)(b * CHAN + ty * 8 + 2 * i + 1)) * LLEN + col] = hi + bhi;
        }
    }
}

// ---------------------------------------------------------------------------
extern "C" void kernel_launch(void* const* d_in, const int* in_sizes, int n_in,
                              void* d_out, int out_size)
{
    const float* nbr  = (const float*)d_in[0];
    const float* ext  = (const float*)d_in[1];
    const float* Wv   = (const float*)d_in[2];
    const float* bv   = (const float*)d_in[3];
    const float* Wo   = (const float*)d_in[4];
    const float* bo   = (const float*)d_in[5];
    const float* Wa   = (const float*)d_in[6];
    const float* ba   = (const float*)d_in[7];
    const float* Wout = (const float*)d_in[8];
    const float* bout = (const float*)d_in[9];
    float* out = (float*)d_out;

    dim3 gproj(256, 5);
    proj_kernel<<<gproj, 256>>>(nbr, ext, Wv, bv, Wo, bo, Wa, ba);

    dim3 gsamp(64, BATCH);
    sample_kernel<<<gsamp, 256>>>();

    out_kernel<<<512, 256>>>(Wout, bout, out);
}

// round 4
// speedup vs baseline: 2.1645x; 2.1645x over previous
#include <cuda_runtime.h>
#include <math.h>

#define BATCH 8
#define CHAN  128
#define HDIM  64
#define WDIM  64
#define LLEN  4096
#define NHEAD 8
#define NPTS  8
#define DHEAD 16

__device__ float g_value[BATCH * LLEN * CHAN];
__device__ float g_off  [BATCH * LLEN * NHEAD * NPTS * 2];
__device__ float g_attn [BATCH * LLEN * NHEAD * NPTS];

// ---------------------------------------------------------------------------
// Kernel 1: fused projections (R2 version — measured 67us, ~fp32 roofline).
// 128l x 64n tile, 256 thr, 8x4 per thread.
// ---------------------------------------------------------------------------
__global__ __launch_bounds__(256)
void proj_kernel(const float* __restrict__ nbr, const float* __restrict__ ext,
                 const float* __restrict__ Wv, const float* __restrict__ bv,
                 const float* __restrict__ Wo, const float* __restrict__ bo,
                 const float* __restrict__ Wa, const float* __restrict__ ba)
{
    __shared__ float As[16][128];
    __shared__ float Bs[16][64];

    const int nt  = blockIdx.y;
    const int b   = blockIdx.x >> 5;
    const int l0  = (blockIdx.x & 31) << 7;
    const int tid = threadIdx.x;
    const int tx  = tid & 15;
    const int ty  = tid >> 4;

    const float* Asrc = (nt < 2) ? nbr : ext;
    const float* Bsrc;
    int bstride, bcol;
    if (nt == 0)      { Bsrc = Wv; bstride = 128; bcol = 0;  }
    else if (nt == 1) { Bsrc = Wv; bstride = 128; bcol = 64; }
    else if (nt == 2) { Bsrc = Wo; bstride = 128; bcol = 0;  }
    else if (nt == 3) { Bsrc = Wo; bstride = 128; bcol = 64; }
    else              { Bsrc = Wa; bstride = 64;  bcol = 0;  }

    float acc[8][4];
    #pragma unroll
    for (int i = 0; i < 8; i++)
        #pragma unroll
        for (int j = 0; j < 4; j++) acc[i][j] = 0.f;

    for (int k0 = 0; k0 < CHAN; k0 += 16) {
        #pragma unroll
        for (int i = 0; i < 2; i++) {
            int fid = tid + i * 256;
            int row = fid >> 5, c4 = (fid & 31) << 2;
            *(float4*)&As[row][c4] =
                *(const float4*)&Asrc[(size_t)(b * CHAN + k0 + row) * LLEN + l0 + c4];
        }
        {
            int row = tid >> 4, c4 = (tid & 15) << 2;
            *(float4*)&Bs[row][c4] =
                *(const float4*)&Bsrc[(k0 + row) * bstride + bcol + c4];
        }
        __syncthreads();

        #pragma unroll
        for (int kk = 0; kk < 16; kk++) {
            float4 a0 = *(float4*)&As[kk][ty * 8];
            float4 a1 = *(float4*)&As[kk][ty * 8 + 4];
            float4 bb = *(float4*)&Bs[kk][tx * 4];
            float av[8] = {a0.x, a0.y, a0.z, a0.w, a1.x, a1.y, a1.z, a1.w};
            float bw[4] = {bb.x, bb.y, bb.z, bb.w};
            #pragma unroll
            for (int i = 0; i < 8; i++)
                #pragma unroll
                for (int j = 0; j < 4; j++)
                    acc[i][j] = fmaf(av[i], bw[j], acc[i][j]);
        }
        __syncthreads();
    }

    if (nt < 2) {
        int n = nt * 64 + tx * 4;
        float4 bia = *(const float4*)&bv[n];
        #pragma unroll
        for (int i = 0; i < 8; i++) {
            int l = l0 + ty * 8 + i;
            float4 v = {acc[i][0] + bia.x, acc[i][1] + bia.y,
                        acc[i][2] + bia.z, acc[i][3] + bia.w};
            *(float4*)&g_value[(size_t)(b * LLEN + l) * 128 + n] = v;
        }
    } else if (nt < 4) {
        int m = (nt - 2) * 64 + tx * 4;
        float4 bia = *(const float4*)&bo[m];
        #pragma unroll
        for (int i = 0; i < 8; i++) {
            int l = l0 + ty * 8 + i;
            float4 v = {10.0f * tanhf(acc[i][0] + bia.x), 10.0f * tanhf(acc[i][1] + bia.y),
                        10.0f * tanhf(acc[i][2] + bia.z), 10.0f * tanhf(acc[i][3] + bia.w)};
            *(float4*)&g_off[(size_t)(b * LLEN + l) * 128 + m] = v;
        }
    } else {
        int m = tx * 4;
        float4 bia = *(const float4*)&ba[m];
        #pragma unroll
        for (int i = 0; i < 8; i++) {
            int l = l0 + ty * 8 + i;
            float4 v = {acc[i][0] + bia.x, acc[i][1] + bia.y,
                        acc[i][2] + bia.z, acc[i][3] + bia.w};
            *(float4*)&g_attn[(size_t)(b * LLEN + l) * 64 + m] = v;
        }
    }
}

// ---------------------------------------------------------------------------
// Kernel 2: fused softmax + bilinear sampling + output projection.
// One block per (b, 8x8 spatial tile), 256 threads, 97KB dynamic smem.
// Phase 1: weights + abs coords -> smem.
// Phase 2: one warp per l, float4 gathers -> s_mid[64][132].
// Phase 3: out[n,l] = mid @ Wout + b_out, transposed store.
// ---------------------------------------------------------------------------
#define MID_STRIDE 132

__global__ __launch_bounds__(256)
void sample_out_kernel(const float* __restrict__ Wout,
                       const float* __restrict__ bout,
                       float* __restrict__ out)
{
    extern __shared__ float sm[];
    float* sw    = sm;                    // 4096
    float* spx   = sm + 4096;             // 4096
    float* spy   = sm + 8192;             // 4096
    float* s_mid = sm + 12288;            // 64*132 = 8448
    float* wtile = sm + 12288 + 8448;     // 32*128 = 4096

    const int b    = blockIdx.y;
    const int tile = blockIdx.x;
    const int x0t  = (tile & 7) * 8;
    const int y0t  = (tile >> 3) * 8;
    const int tid  = threadIdx.x;

    // ---- Phase 1: softmax + absolute sample coords ----
    #pragma unroll
    for (int i = 0; i < 2; i++) {
        int task  = tid + i * 256;
        int l_loc = task >> 3;
        int h     = task & 7;
        int lx = x0t + (l_loc & 7);
        int ly = y0t + (l_loc >> 3);
        size_t bl = (size_t)b * LLEN + ly * WDIM + lx;

        const float* op = g_off + bl * 128 + h * 16;
        float4 o0 = *(const float4*)(op);
        float4 o1 = *(const float4*)(op + 4);
        float4 o2 = *(const float4*)(op + 8);
        float4 o3 = *(const float4*)(op + 12);
        float ox[8] = {o0.x, o0.z, o1.x, o1.z, o2.x, o2.z, o3.x, o3.z};
        float oy[8] = {o0.y, o0.w, o1.y, o1.w, o2.y, o2.w, o3.y, o3.w};

        const float* ap = g_attn + bl * 64 + h * 8;
        float4 g0 = *(const float4*)(ap);
        float4 g1 = *(const float4*)(ap + 4);
        float lg[8] = {g0.x, g0.y, g0.z, g0.w, g1.x, g1.y, g1.z, g1.w};

        float m = -1e30f;
        #pragma unroll
        for (int p = 0; p < 8; p++) m = fmaxf(m, lg[p]);
        float e[8], s = 0.f;
        #pragma unroll
        for (int p = 0; p < 8; p++) { e[p] = __expf(lg[p] - m); s += e[p]; }
        float inv = 1.0f / s;

        int base = l_loc * 64 + h * 8;
        #pragma unroll
        for (int p = 0; p < 8; p++) {
            sw [base + p] = e[p] * inv;
            spx[base + p] = (float)lx + ox[p];
            spy[base + p] = (float)ly + oy[p];
        }
    }
    __syncthreads();

    // ---- Phase 2: one warp per l, float4 gathers ----
    const int warp = tid >> 5;
    const int lane = tid & 31;
    const int h    = lane >> 2;
    const int ch   = h * 16 + (lane & 3) * 4;
    const float* vbase = g_value + (size_t)b * LLEN * CHAN + ch;

    #pragma unroll 1
    for (int it = 0; it < 8; it++) {
        int l_loc = it * 8 + warp;

        float4 acc = {0.f, 0.f, 0.f, 0.f};
        int sbase = l_loc * 64 + h * 8;
        #pragma unroll
        for (int p = 0; p < 8; p++) {
            float wt = sw [sbase + p];
            float px = spx[sbase + p];
            float py = spy[sbase + p];
            float x0f = floorf(px), y0f = floorf(py);
            float fx = px - x0f, fy = py - y0f;
            int x0 = (int)x0f, y0 = (int)y0f;

            int xc0 = min(max(x0, 0), WDIM - 1);
            int xc1 = min(max(x0 + 1, 0), WDIM - 1);
            int yc0 = min(max(y0, 0), HDIM - 1);
            int yc1 = min(max(y0 + 1, 0), HDIM - 1);
            float mx0 = (x0 >= 0  && x0 < WDIM)      ? 1.f : 0.f;
            float mx1 = (x0 >= -1 && x0 < WDIM - 1)  ? 1.f : 0.f;
            float my0 = (y0 >= 0  && y0 < HDIM)      ? 1.f : 0.f;
            float my1 = (y0 >= -1 && y0 < HDIM - 1)  ? 1.f : 0.f;

            float gx0 = 1.f - fx, gy0 = 1.f - fy;
            float w00 = wt * gx0 * gy0 * mx0 * my0;
            float w10 = wt * fx  * gy0 * mx1 * my0;
            float w01 = wt * gx0 * fy  * mx0 * my1;
            float w11 = wt * fx  * fy  * mx1 * my1;

            int r0 = yc0 * WDIM, r1 = yc1 * WDIM;
            float4 v00 = *(const float4*)(vbase + (size_t)(r0 + xc0) * CHAN);
            float4 v10 = *(const float4*)(vbase + (size_t)(r0 + xc1) * CHAN);
            float4 v01 = *(const float4*)(vbase + (size_t)(r1 + xc0) * CHAN);
            float4 v11 = *(const float4*)(vbase + (size_t)(r1 + xc1) * CHAN);

            acc.x = fmaf(w00, v00.x, fmaf(w10, v10.x, fmaf(w01, v01.x, fmaf(w11, v11.x, acc.x))));
            acc.y = fmaf(w00, v00.y, fmaf(w10, v10.y, fmaf(w01, v01.y, fmaf(w11, v11.y, acc.y))));
            acc.z = fmaf(w00, v00.z, fmaf(w10, v10.z, fmaf(w01, v01.z, fmaf(w11, v11.z, acc.z))));
            acc.w = fmaf(w00, v00.w, fmaf(w10, v10.w, fmaf(w01, v01.w, fmaf(w11, v11.w, acc.w))));
        }
        *(float4*)&s_mid[l_loc * MID_STRIDE + ch] = acc;
    }
    __syncthreads();

    // ---- Phase 3: output projection, 64l x 128n, k=128 in 4 tiles of 32 ----
    const int tx = tid & 15;         // l group (strided 16)
    const int ty = tid >> 4;         // 8 consecutive n
    float oacc[8][4];
    #pragma unroll
    for (int i = 0; i < 8; i++)
        #pragma unroll
        for (int j = 0; j < 4; j++) oacc[i][j] = 0.f;

    for (int k0 = 0; k0 < CHAN; k0 += 32) {
        #pragma unroll
        for (int i = 0; i < 4; i++) {
            int fid = tid + i * 256;
            int row = fid >> 5, c4 = (fid & 31) << 2;
            *(float4*)&wtile[row * 128 + c4] =
                *(const float4*)&Wout[(k0 + row) * 128 + c4];
        }
        __syncthreads();

        #pragma unroll
        for (int kk = 0; kk < 32; kk++) {
            float a[4];
            #pragma unroll
            for (int j = 0; j < 4; j++)
                a[j] = s_mid[(tx + 16 * j) * MID_STRIDE + k0 + kk];
            float4 w0 = *(float4*)&wtile[kk * 128 + ty * 8];
            float4 w1 = *(float4*)&wtile[kk * 128 + ty * 8 + 4];
            float wv[8] = {w0.x, w0.y, w0.z, w0.w, w1.x, w1.y, w1.z, w1.w};
            #pragma unroll
            for (int i = 0; i < 8; i++)
                #pragma unroll
                for (int j = 0; j < 4; j++)
                    oacc[i][j] = fmaf(wv[i], a[j], oacc[i][j]);
        }
        __syncthreads();
    }

    #pragma unroll
    for (int i = 0; i < 8; i++) {
        int n = ty * 8 + i;
        float bb = bout[n];
        #pragma unroll
        for (int j = 0; j < 4; j++) {
            int l_loc = tx + 16 * j;
            int lx = x0t + (l_loc & 7);
            int ly = y0t + (l_loc >> 3);
            out[((size_t)(b * CHAN + n)) * LLEN + ly * WDIM + lx] = oacc[i][j] + bb;
        }
    }
}

// ---------------------------------------------------------------------------
extern "C" void kernel_launch(void* const* d_in, const int* in_sizes, int n_in,
                              void* d_out, int out_size)
{
    const float* nbr  = (const float*)d_in[0];
    const float* ext  = (const float*)d_in[1];
    const float* Wv   = (const float*)d_in[2];
    const float* bv   = (const float*)d_in[3];
    const float* Wo   = (const float*)d_in[4];
    const float* bo   = (const float*)d_in[5];
    const float* Wa   = (const float*)d_in[6];
    const float* ba   = (const float*)d_in[7];
    const float* Wout = (const float*)d_in[8];
    const float* bout = (const float*)d_in[9];
    float* out = (float*)d_out;

    static int configured = 0;
    const int smem_bytes = (12288 + 8448 + 4096) * 4;   // 99328 B
    if (!configured) {
        cudaFuncSetAttribute(sample_out_kernel,
                             cudaFuncAttributeMaxDynamicSharedMemorySize, smem_bytes);
        configured = 1;
    }

    dim3 gproj(256, 5);
    proj_kernel<<<gproj, 256>>>(nbr, ext, Wv, bv, Wo, bo, Wa, ba);

    dim3 gsamp(64, BATCH);
    sample_out_kernel<<<gsamp, 256, smem_bytes>>>(Wout, bout, out);
}